// round 1
// baseline (speedup 1.0000x reference)
#include <cuda_runtime.h>
#include <math.h>

#define Nn 10000
#define Ee 128000

// ---------------- scratch (device globals: allocation-free) ----------------
__device__ float g_h[(size_t)Nn * 512];        // [n][0:128]=h0, [128+k*128+u]=h1[u,k]
__device__ float g_w[(size_t)Ee * 512];        // edge MLP output
__device__ float g_M[(size_t)Nn * 1024];       // [0:256]=M0, [256+k*256+c]=M1[c,k]
__device__ float g_dens[Nn];

// ---------------- clear accumulators ----------------
__global__ void clear_kernel() {
    int stride = gridDim.x * blockDim.x;
    int i = blockIdx.x * blockDim.x + threadIdx.x;
    float4 z = make_float4(0.f, 0.f, 0.f, 0.f);
    for (int p = i; p < Nn * 1024 / 4; p += stride) ((float4*)g_M)[p] = z;
    for (int p = i; p < Nn; p += stride) g_dens[p] = 0.f;
}

// ---------------- edge density + segment sum ----------------
__global__ void density_kernel(const float* __restrict__ ef,
                               const float* __restrict__ Wd,
                               const int* __restrict__ eidx) {
    float w[8];
#pragma unroll
    for (int k = 0; k < 8; k++) w[k] = __ldg(&Wd[k]);
    int stride = gridDim.x * blockDim.x;
    for (int e = blockIdx.x * blockDim.x + threadIdx.x; e < Ee; e += stride) {
        float t = 0.f;
#pragma unroll
        for (int k = 0; k < 8; k++) t += ef[(size_t)e * 8 + k] * w[k];
        t *= 0.35355339059327373f;  // 1/sqrt(8)
        atomicAdd(&g_dens[eidx[Ee + e]], tanhf(t * t));
    }
}

// ---------------- node kernel: up-projection (h) + skip (sc) ----------------
// grid (79, 4): blockIdx.y = j slab (0: x0 path / W*0 ; 1..3: x1[:,:,j-1] / W*1)
__global__ void node_kernel(const float* __restrict__ nf, const float* __restrict__ na,
                            const float* __restrict__ Wup0, const float* __restrict__ Wup1,
                            const float* __restrict__ Wsk0, const float* __restrict__ Wsk1,
                            float* __restrict__ sc_out) {
    extern __shared__ float sm[];
    float* xs  = sm;           // 128*128
    float* ats = xs + 16384;   // 128*12
    float* ych = ats + 1536;   // 32*132 (padded transposed A chunk)
    float* wb  = ych + 4224;   // 32*128 (B chunk)

    const int tid = threadIdx.x;
    const int j = blockIdx.y;
    const int nb = blockIdx.x * 128;

    if (j == 0) {
        for (int p = tid; p < 4096; p += 512) {
            int n = p >> 5, u4 = (p & 31) << 2;
            int gn = nb + n;
            float4 v = make_float4(0.f, 0.f, 0.f, 0.f);
            if (gn < Nn) v = *(const float4*)(nf + (size_t)gn * 512 + u4);
            *(float4*)(xs + n * 128 + u4) = v;
        }
    } else {
        int kc2 = j - 1;
        for (int p = tid; p < 16384; p += 512) {
            int n = p >> 7, u = p & 127;
            int gn = nb + n;
            xs[p] = (gn < Nn) ? nf[(size_t)gn * 512 + 128 + u * 3 + kc2] : 0.f;
        }
    }
    for (int p = tid; p < 1280; p += 512) {
        int n = p / 10, a = p - n * 10;
        int gn = nb + n;
        ats[n * 12 + a] = (gn < Nn) ? na[(size_t)gn * 10 + a] : 0.f;
    }
    __syncthreads();

    const int tv = tid & 15, tn = tid >> 4;
    const int v0 = tv * 8, n0 = tn * 4;
    const float* Wup = (j == 0) ? Wup0 : Wup1;
    const float* Wsk = (j == 0) ? Wsk0 : Wsk1;

    float acc[4][8];
#pragma unroll
    for (int i = 0; i < 4; i++)
#pragma unroll
        for (int q = 0; q < 8; q++) acc[i][q] = 0.f;

    // ---- up projection: K = 128 ----
    for (int kc = 0; kc < 4; kc++) {
        for (int p = tid; p < 1024; p += 512)
            *(float4*)(wb + p * 4) = *(const float4*)(Wup + kc * 4096 + p * 4);
        for (int p = tid; p < 4096; p += 512) {
            int kk = p & 31, n = p >> 5;
            ych[kk * 132 + n] = xs[n * 128 + kc * 32 + kk];
        }
        __syncthreads();
#pragma unroll
        for (int kk = 0; kk < 32; kk++) {
            float4 a4 = *(float4*)(ych + kk * 132 + n0);
            float4 b0 = *(float4*)(wb + kk * 128 + v0);
            float4 b1 = *(float4*)(wb + kk * 128 + v0 + 4);
            float av[4] = {a4.x, a4.y, a4.z, a4.w};
            float bv[8] = {b0.x, b0.y, b0.z, b0.w, b1.x, b1.y, b1.z, b1.w};
#pragma unroll
            for (int i = 0; i < 4; i++)
#pragma unroll
                for (int q = 0; q < 8; q++) acc[i][q] += av[i] * bv[q];
        }
        __syncthreads();
    }
    {
        const float s = 0.08838834764831845f;  // 1/sqrt(128)
#pragma unroll
        for (int i = 0; i < 4; i++) {
            int gn = nb + n0 + i;
            if (gn < Nn) {
                float* hp = g_h + (size_t)gn * 512 + j * 128 + v0;
#pragma unroll
                for (int q = 0; q < 8; q++) hp[q] = acc[i][q] * s;
            }
        }
    }

#pragma unroll
    for (int i = 0; i < 4; i++)
#pragma unroll
        for (int q = 0; q < 8; q++) acc[i][q] = 0.f;

    // ---- skip: K = 1280 over (u,a); A built on the fly = x[n,u]*attr[n,a] ----
    for (int kc = 0; kc < 40; kc++) {
        for (int p = tid; p < 1024; p += 512)
            *(float4*)(wb + p * 4) = *(const float4*)(Wsk + kc * 4096 + p * 4);
        for (int p = tid; p < 4096; p += 512) {
            int kk = p & 31, n = p >> 5;
            int ua = kc * 32 + kk;
            int u = ua / 10, a = ua - u * 10;
            ych[kk * 132 + n] = xs[n * 128 + u] * ats[n * 12 + a];
        }
        __syncthreads();
#pragma unroll
        for (int kk = 0; kk < 32; kk++) {
            float4 a4 = *(float4*)(ych + kk * 132 + n0);
            float4 b0 = *(float4*)(wb + kk * 128 + v0);
            float4 b1 = *(float4*)(wb + kk * 128 + v0 + 4);
            float av[4] = {a4.x, a4.y, a4.z, a4.w};
            float bv[8] = {b0.x, b0.y, b0.z, b0.w, b1.x, b1.y, b1.z, b1.w};
#pragma unroll
            for (int i = 0; i < 4; i++)
#pragma unroll
                for (int q = 0; q < 8; q++) acc[i][q] += av[i] * bv[q];
        }
        __syncthreads();
    }
    {
        const float s = 0.027950849718747373f;  // 1/sqrt(1280)
#pragma unroll
        for (int i = 0; i < 4; i++) {
            int gn = nb + n0 + i;
            if (gn < Nn) {
                float* so = sc_out + (size_t)gn * 512;
                if (j == 0) {
#pragma unroll
                    for (int q = 0; q < 8; q++) so[v0 + q] = acc[i][q] * s;
                } else {
#pragma unroll
                    for (int q = 0; q < 8; q++) so[128 + (v0 + q) * 3 + (j - 1)] = acc[i][q] * s;
                }
            }
        }
    }
}

// ---------------- edge MLP: 8 -> 64 -> 64 -> 64 -> 512 ----------------
__global__ void mlp_kernel(const float* __restrict__ ef, const float* __restrict__ R0,
                           const float* __restrict__ R1, const float* __restrict__ R2,
                           const float* __restrict__ R3) {
    extern __shared__ float sm[];
    float* efs = sm;            // 1024
    float* r0s = efs + 1024;    // 512
    float* r1s = r0s + 512;     // 4096
    float* r2s = r1s + 4096;    // 4096
    float* A1  = r2s + 4096;    // 8192
    float* A2  = A1 + 8192;     // 8192
    float* r3b = A2 + 8192;     // 8192
    const int tid = threadIdx.x;
    const int eb = blockIdx.x * 128;

    for (int p = tid; p < 256; p += 512)
        ((float4*)efs)[p] = ((const float4*)(ef + (size_t)eb * 8))[p];
    for (int p = tid; p < 512; p += 512) r0s[p] = R0[p];
    for (int p = tid; p < 4096; p += 512) { r1s[p] = R1[p]; r2s[p] = R2[p]; }
    __syncthreads();

    // L1: silu(ef @ R0 / sqrt(8))
    for (int p = tid; p < 8192; p += 512) {
        int e = p >> 6, c = p & 63;
        float s = 0.f;
#pragma unroll
        for (int k = 0; k < 8; k++) s += efs[e * 8 + k] * r0s[k * 64 + c];
        s *= 0.35355339059327373f;
        A1[p] = s / (1.f + __expf(-s));
    }
    __syncthreads();

    const int tc = tid & 15, te = tid >> 4;
    // L2: A2 = silu(A1 @ R1 / 8)
    {
        int c0 = tc * 4, e0 = te * 4;
        float acc2[4][4];
#pragma unroll
        for (int i = 0; i < 4; i++)
#pragma unroll
            for (int q = 0; q < 4; q++) acc2[i][q] = 0.f;
        for (int k = 0; k < 64; k++) {
            float4 b = *(float4*)(r1s + k * 64 + c0);
#pragma unroll
            for (int i = 0; i < 4; i++) {
                float a = A1[(e0 + i) * 64 + k];
                acc2[i][0] += a * b.x; acc2[i][1] += a * b.y;
                acc2[i][2] += a * b.z; acc2[i][3] += a * b.w;
            }
        }
#pragma unroll
        for (int i = 0; i < 4; i++)
#pragma unroll
            for (int q = 0; q < 4; q++) {
                float s = acc2[i][q] * 0.125f;
                A2[(e0 + i) * 64 + c0 + q] = s / (1.f + __expf(-s));
            }
    }
    __syncthreads();
    // L3: A1 = silu(A2 @ R2 / 8)
    {
        int c0 = tc * 4, e0 = te * 4;
        float acc2[4][4];
#pragma unroll
        for (int i = 0; i < 4; i++)
#pragma unroll
            for (int q = 0; q < 4; q++) acc2[i][q] = 0.f;
        for (int k = 0; k < 64; k++) {
            float4 b = *(float4*)(r2s + k * 64 + c0);
#pragma unroll
            for (int i = 0; i < 4; i++) {
                float a = A2[(e0 + i) * 64 + k];
                acc2[i][0] += a * b.x; acc2[i][1] += a * b.y;
                acc2[i][2] += a * b.z; acc2[i][3] += a * b.w;
            }
        }
        __syncthreads();  // all reads of A1 in L2 done before overwrite? (L2 read A1; ensure done)
#pragma unroll
        for (int i = 0; i < 4; i++)
#pragma unroll
            for (int q = 0; q < 4; q++) {
                float s = acc2[i][q] * 0.125f;
                A1[(e0 + i) * 64 + c0 + q] = s / (1.f + __expf(-s));
            }
    }
    __syncthreads();
    // L4: w = A1 @ R3 / 8, 4 column chunks of 128
    {
        int c0 = tc * 8, e0 = te * 4;
        for (int ch = 0; ch < 4; ch++) {
            for (int p = tid; p < 8192; p += 512) {
                int kk = p >> 7, c = p & 127;
                r3b[p] = R3[kk * 512 + ch * 128 + c];
            }
            __syncthreads();
            float acc[4][8];
#pragma unroll
            for (int i = 0; i < 4; i++)
#pragma unroll
                for (int q = 0; q < 8; q++) acc[i][q] = 0.f;
            for (int k = 0; k < 64; k++) {
                float4 b0 = *(float4*)(r3b + k * 128 + c0);
                float4 b1 = *(float4*)(r3b + k * 128 + c0 + 4);
#pragma unroll
                for (int i = 0; i < 4; i++) {
                    float a = A1[(e0 + i) * 64 + k];
                    acc[i][0] += a * b0.x; acc[i][1] += a * b0.y;
                    acc[i][2] += a * b0.z; acc[i][3] += a * b0.w;
                    acc[i][4] += a * b1.x; acc[i][5] += a * b1.y;
                    acc[i][6] += a * b1.z; acc[i][7] += a * b1.w;
                }
            }
#pragma unroll
            for (int i = 0; i < 4; i++) {
                float* wp = g_w + (size_t)(eb + e0 + i) * 512 + ch * 128 + c0;
                float4 o0 = make_float4(acc[i][0] * 0.125f, acc[i][1] * 0.125f,
                                        acc[i][2] * 0.125f, acc[i][3] * 0.125f);
                float4 o1 = make_float4(acc[i][4] * 0.125f, acc[i][5] * 0.125f,
                                        acc[i][6] * 0.125f, acc[i][7] * 0.125f);
                *(float4*)wp = o0;
                *(float4*)(wp + 4) = o1;
            }
            __syncthreads();
        }
    }
}

// ---------------- edge message construction + scatter ----------------
__global__ void msg_kernel(const float* __restrict__ ea, const int* __restrict__ eidx) {
    const int u = threadIdx.x & 127;
    const int le = threadIdx.x >> 7;
    for (int e = blockIdx.x * 4 + le; e < Ee; e += gridDim.x * 4) {
        int s = eidx[e];
        int r = eidx[Ee + e];
        const float4 y = *(const float4*)(ea + (size_t)e * 4);
        const float* wr = g_w + (size_t)e * 512;
        float w1 = wr[u], w2 = wr[128 + u], w3 = wr[256 + u], w4 = wr[384 + u];
        const float* hr = g_h + (size_t)s * 512;
        float hs0 = hr[u];
        float h1a = hr[128 + u], h1b = hr[256 + u], h1c = hr[384 + u];
        float* Mr = g_M + (size_t)r * 1024;
        atomicAdd(Mr + u, w1 * hs0 * y.x);
        float dot3 = h1a * y.y + h1b * y.z + h1c * y.w;
        atomicAdd(Mr + 128 + u, w4 * dot3 * 0.5773502691896258f);  // 1/sqrt(3)
        float t2 = w2 * hs0;
        atomicAdd(Mr + 256 + u, t2 * y.y);
        atomicAdd(Mr + 384 + u, w3 * h1a * y.x);
        atomicAdd(Mr + 512 + u, t2 * y.z);
        atomicAdd(Mr + 640 + u, w3 * h1b * y.x);
        atomicAdd(Mr + 768 + u, t2 * y.w);
        atomicAdd(Mr + 896 + u, w3 * h1c * y.x);
    }
}

// ---------------- final linear + density divide -> message output ----------------
// grid (79, 4): j=0 -> out0 (W_lin0), j=1..3 -> out1[:,:,j-1] (W_lin1)
__global__ void lin_kernel(const float* __restrict__ Wl0, const float* __restrict__ Wl1,
                           float* __restrict__ msg_out) {
    extern __shared__ float sm[];
    float* wls = sm;            // 256*128
    float* ych = wls + 32768;   // 32*132
    const int tid = threadIdx.x;
    const int j = blockIdx.y;
    const int nb = blockIdx.x * 128;
    const float* Wl = (j == 0) ? Wl0 : Wl1;
    for (int p = tid; p < 8192; p += 512)
        ((float4*)wls)[p] = ((const float4*)Wl)[p];

    const int tv = tid & 15, tn = tid >> 4;
    const int v0 = tv * 8, n0 = tn * 4;
    float acc[4][8];
#pragma unroll
    for (int i = 0; i < 4; i++)
#pragma unroll
        for (int q = 0; q < 8; q++) acc[i][q] = 0.f;

    for (int kc = 0; kc < 8; kc++) {
        __syncthreads();
        for (int p = tid; p < 4096; p += 512) {
            int kk = p & 31, n = p >> 5;
            int gn = nb + n;
            ych[kk * 132 + n] =
                (gn < Nn) ? g_M[(size_t)gn * 1024 + j * 256 + kc * 32 + kk] : 0.f;
        }
        __syncthreads();
#pragma unroll
        for (int kk = 0; kk < 32; kk++) {
            float4 a4 = *(float4*)(ych + kk * 132 + n0);
            float4 b0 = *(float4*)(wls + (kc * 32 + kk) * 128 + v0);
            float4 b1 = *(float4*)(wls + (kc * 32 + kk) * 128 + v0 + 4);
            float av[4] = {a4.x, a4.y, a4.z, a4.w};
            float bv[8] = {b0.x, b0.y, b0.z, b0.w, b1.x, b1.y, b1.z, b1.w};
#pragma unroll
            for (int i = 0; i < 4; i++)
#pragma unroll
                for (int q = 0; q < 8; q++) acc[i][q] += av[i] * bv[q];
        }
    }
#pragma unroll
    for (int i = 0; i < 4; i++) {
        int gn = nb + n0 + i;
        if (gn < Nn) {
            float inv = 0.0625f / (g_dens[gn] + 1.f);  // 1/sqrt(256) / denom
#pragma unroll
            for (int q = 0; q < 8; q++)
                msg_out[(size_t)gn * 512 + (size_t)(v0 + q) * 4 + j] = acc[i][q] * inv;
        }
    }
}

extern "C" void kernel_launch(void* const* d_in, const int* in_sizes, int n_in,
                              void* d_out, int out_size) {
    const float* na   = (const float*)d_in[0];
    const float* nf   = (const float*)d_in[1];
    const float* ea   = (const float*)d_in[2];
    const float* ef   = (const float*)d_in[3];
    const int*   eidx = (const int*)d_in[4];
    const float* Wup0 = (const float*)d_in[5];
    const float* Wup1 = (const float*)d_in[6];
    const float* R0   = (const float*)d_in[7];
    const float* R1   = (const float*)d_in[8];
    const float* R2   = (const float*)d_in[9];
    const float* R3   = (const float*)d_in[10];
    const float* Wd   = (const float*)d_in[11];
    const float* Wl0  = (const float*)d_in[12];
    const float* Wl1  = (const float*)d_in[13];
    const float* Wsk0 = (const float*)d_in[14];
    const float* Wsk1 = (const float*)d_in[15];
    float* out = (float*)d_out;
    float* msg_out = out;                       // message: (N,128,4)
    float* sc_out  = out + (size_t)Nn * 512;    // sc: (N,512)

    cudaFuncSetAttribute(node_kernel, cudaFuncAttributeMaxDynamicSharedMemorySize, 104960);
    cudaFuncSetAttribute(mlp_kernel,  cudaFuncAttributeMaxDynamicSharedMemorySize, 137216);
    cudaFuncSetAttribute(lin_kernel,  cudaFuncAttributeMaxDynamicSharedMemorySize, 147968);

    clear_kernel<<<2048, 256>>>();
    density_kernel<<<512, 256>>>(ef, Wd, eidx);
    node_kernel<<<dim3(79, 4), 512, 104960>>>(nf, na, Wup0, Wup1, Wsk0, Wsk1, sc_out);
    mlp_kernel<<<1000, 512, 137216>>>(ef, R0, R1, R2, R3);
    msg_kernel<<<4096, 512>>>(ea, eidx);
    lin_kernel<<<dim3(79, 4), 512, 147968>>>(Wl0, Wl1, msg_out);
}

// round 2
// speedup vs baseline: 1.2536x; 1.2536x over previous
#include <cuda_runtime.h>
#include <math.h>

#define Nn 10000
#define Ee 128000

// ---------------- scratch (device globals: allocation-free) ----------------
__device__ float g_h[(size_t)Nn * 512];   // [n][0:128]=h0, [128+k*128+u]=h1[u,k]
__device__ float g_M[(size_t)Nn * 1024];  // [0:256]=M0, [256+k*256+c]=M1[c,k]
__device__ float g_dens[Nn];

// ---------------- clear accumulators ----------------
__global__ void clear_kernel() {
    int stride = gridDim.x * blockDim.x;
    int i = blockIdx.x * blockDim.x + threadIdx.x;
    float4 z = make_float4(0.f, 0.f, 0.f, 0.f);
    for (int p = i; p < Nn * 1024 / 4; p += stride) ((float4*)g_M)[p] = z;
    for (int p = i; p < Nn; p += stride) g_dens[p] = 0.f;
}

// ---------------- edge density + segment sum ----------------
__global__ void density_kernel(const float* __restrict__ ef,
                               const float* __restrict__ Wd,
                               const int* __restrict__ eidx) {
    float w[8];
#pragma unroll
    for (int k = 0; k < 8; k++) w[k] = __ldg(&Wd[k]);
    int stride = gridDim.x * blockDim.x;
    for (int e = blockIdx.x * blockDim.x + threadIdx.x; e < Ee; e += stride) {
        float t = 0.f;
#pragma unroll
        for (int k = 0; k < 8; k++) t += ef[(size_t)e * 8 + k] * w[k];
        t *= 0.35355339059327373f;  // 1/sqrt(8)
        atomicAdd(&g_dens[eidx[Ee + e]], tanhf(t * t));
    }
}

// ---------------- node kernel: up-projection (h) + skip (sc) ----------------
// grid (79, 4): blockIdx.y = j slab (0: x0/W*0 ; 1..3: x1[:,:,j-1]/W*1)
// 256 threads, 128 nodes x 128 v tile, 8x8 micro-tile -> 2 blocks/SM
__global__ __launch_bounds__(256) void node_kernel(
        const float* __restrict__ nf, const float* __restrict__ na,
        const float* __restrict__ Wup0, const float* __restrict__ Wup1,
        const float* __restrict__ Wsk0, const float* __restrict__ Wsk1,
        float* __restrict__ sc_out) {
    extern __shared__ float sm[];
    float* xs  = sm;           // 128*128 = 16384
    float* ats = xs + 16384;   // 128*12  = 1536
    float* ych = ats + 1536;   // 32*132  = 4224
    float* wb  = ych + 4224;   // 32*128  = 4096

    const int tid = threadIdx.x;
    const int j = blockIdx.y;
    const int nb = blockIdx.x * 128;

    if (j == 0) {
        for (int p = tid; p < 4096; p += 256) {
            int n = p >> 5, u4 = (p & 31) << 2;
            int gn = nb + n;
            float4 v = make_float4(0.f, 0.f, 0.f, 0.f);
            if (gn < Nn) v = *(const float4*)(nf + (size_t)gn * 512 + u4);
            *(float4*)(xs + n * 128 + u4) = v;
        }
    } else {
        int kc2 = j - 1;
        for (int p = tid; p < 16384; p += 256) {
            int n = p >> 7, u = p & 127;
            int gn = nb + n;
            xs[p] = (gn < Nn) ? nf[(size_t)gn * 512 + 128 + u * 3 + kc2] : 0.f;
        }
    }
    for (int p = tid; p < 1280; p += 256) {
        int n = p / 10, a = p - n * 10;
        int gn = nb + n;
        ats[n * 12 + a] = (gn < Nn) ? na[(size_t)gn * 10 + a] : 0.f;
    }
    __syncthreads();

    const int tv = tid & 15, tn = tid >> 4;
    const int v0 = tv * 8, n0 = tn * 8;
    const float* Wup = (j == 0) ? Wup0 : Wup1;
    const float* Wsk = (j == 0) ? Wsk0 : Wsk1;

    float acc[8][8];
#pragma unroll
    for (int i = 0; i < 8; i++)
#pragma unroll
        for (int q = 0; q < 8; q++) acc[i][q] = 0.f;

    // ---- up projection: K = 128 ----
    for (int kc = 0; kc < 4; kc++) {
        for (int p = tid; p < 1024; p += 256)
            *(float4*)(wb + p * 4) = *(const float4*)(Wup + kc * 4096 + p * 4);
        for (int p = tid; p < 4096; p += 256) {
            int kk = p & 31, n = p >> 5;
            ych[kk * 132 + n] = xs[n * 128 + kc * 32 + kk];
        }
        __syncthreads();
#pragma unroll 8
        for (int kk = 0; kk < 32; kk++) {
            float4 a0 = *(float4*)(ych + kk * 132 + n0);
            float4 a1 = *(float4*)(ych + kk * 132 + n0 + 4);
            float4 b0 = *(float4*)(wb + kk * 128 + v0);
            float4 b1 = *(float4*)(wb + kk * 128 + v0 + 4);
            float av[8] = {a0.x, a0.y, a0.z, a0.w, a1.x, a1.y, a1.z, a1.w};
            float bv[8] = {b0.x, b0.y, b0.z, b0.w, b1.x, b1.y, b1.z, b1.w};
#pragma unroll
            for (int i = 0; i < 8; i++)
#pragma unroll
                for (int q = 0; q < 8; q++) acc[i][q] += av[i] * bv[q];
        }
        __syncthreads();
    }
    {
        const float s = 0.08838834764831845f;  // 1/sqrt(128)
#pragma unroll
        for (int i = 0; i < 8; i++) {
            int gn = nb + n0 + i;
            if (gn < Nn) {
                float* hp = g_h + (size_t)gn * 512 + j * 128 + v0;
#pragma unroll
                for (int q = 0; q < 8; q++) hp[q] = acc[i][q] * s;
            }
        }
    }

#pragma unroll
    for (int i = 0; i < 8; i++)
#pragma unroll
        for (int q = 0; q < 8; q++) acc[i][q] = 0.f;

    // ---- skip: K = 1280 over (u,a); A built on the fly = x[n,u]*attr[n,a] ----
    for (int kc = 0; kc < 40; kc++) {
        for (int p = tid; p < 1024; p += 256)
            *(float4*)(wb + p * 4) = *(const float4*)(Wsk + kc * 4096 + p * 4);
        for (int p = tid; p < 4096; p += 256) {
            int kk = p & 31, n = p >> 5;
            int ua = kc * 32 + kk;
            int u = ua / 10, a = ua - u * 10;
            ych[kk * 132 + n] = xs[n * 128 + u] * ats[n * 12 + a];
        }
        __syncthreads();
#pragma unroll 8
        for (int kk = 0; kk < 32; kk++) {
            float4 a0 = *(float4*)(ych + kk * 132 + n0);
            float4 a1 = *(float4*)(ych + kk * 132 + n0 + 4);
            float4 b0 = *(float4*)(wb + kk * 128 + v0);
            float4 b1 = *(float4*)(wb + kk * 128 + v0 + 4);
            float av[8] = {a0.x, a0.y, a0.z, a0.w, a1.x, a1.y, a1.z, a1.w};
            float bv[8] = {b0.x, b0.y, b0.z, b0.w, b1.x, b1.y, b1.z, b1.w};
#pragma unroll
            for (int i = 0; i < 8; i++)
#pragma unroll
                for (int q = 0; q < 8; q++) acc[i][q] += av[i] * bv[q];
        }
        __syncthreads();
    }
    {
        const float s = 0.027950849718747373f;  // 1/sqrt(1280)
#pragma unroll
        for (int i = 0; i < 8; i++) {
            int gn = nb + n0 + i;
            if (gn < Nn) {
                float* so = sc_out + (size_t)gn * 512;
                if (j == 0) {
#pragma unroll
                    for (int q = 0; q < 8; q++) so[v0 + q] = acc[i][q] * s;
                } else {
#pragma unroll
                    for (int q = 0; q < 8; q++) so[128 + (v0 + q) * 3 + (j - 1)] = acc[i][q] * s;
                }
            }
        }
    }
}

// ---------------- fused edge kernel: MLP (8->64->64->64->512) + scatter ----
// 512 threads, 128 edges per block. The 512-wide last layer is computed in
// 4 chunks of 128 columns; chunk ch == w_{ch+1}, whose scatter contribution
// is independent, so each chunk is scattered immediately after its GEMM.
__global__ __launch_bounds__(512) void edge_kernel(
        const float* __restrict__ ef, const float* __restrict__ ea,
        const int* __restrict__ eidx,
        const float* __restrict__ R0, const float* __restrict__ R1,
        const float* __restrict__ R2, const float* __restrict__ R3) {
    extern __shared__ float sm[];
    float* s_ef = sm;             // 1024
    float* s_r0 = sm + 1024;      // 512
    float* s_y  = sm + 1536;      // 512
    int*   s_si = (int*)(sm + 2048);  // 128
    int*   s_ri = (int*)(sm + 2176);  // 128
    float* At_a = sm + 2304;      // 64*132 = 8448  (A^T, [k][e])
    float* At_b = At_a + 8448;    // 8448
    float* s_B  = At_b + 8448;    // 8448 (R1 / R2 as 64x64, R3 chunk as 64x128)
    float* s_w  = s_B + 8448;     // 128*132 = 16896 ([u][e])
    // total 44544 floats = 178176 B

    const int tid = threadIdx.x;
    const int eb = blockIdx.x * 128;

    // ---- stage inputs ----
    for (int p = tid; p < 256; p += 512)
        ((float4*)s_ef)[p] = ((const float4*)(ef + (size_t)eb * 8))[p];
    for (int p = tid; p < 128; p += 512)
        ((float4*)s_y)[p] = ((const float4*)(ea + (size_t)eb * 4))[p];
    if (tid < 128) {
        s_si[tid] = eidx[eb + tid];
        s_ri[tid] = eidx[Ee + eb + tid];
    }
    if (tid < 512) s_r0[tid] = R0[tid];
    for (int p = tid; p < 4096; p += 512) s_B[p] = R1[p];
    __syncthreads();

    // ---- L1: At_a[c][e] = silu(ef[e] . R0[:,c] / sqrt(8)) ----
    for (int p = tid; p < 8192; p += 512) {
        int c = p >> 7, e = p & 127;
        float s = 0.f;
#pragma unroll
        for (int k = 0; k < 8; k++) s += s_ef[e * 8 + k] * s_r0[k * 64 + c];
        s *= 0.35355339059327373f;
        At_a[c * 132 + e] = s / (1.f + __expf(-s));
    }
    __syncthreads();

    const int te = tid & 31;   // e-tile: e0 = 4*te
    const int tc = tid >> 5;   // c-tile: c0 = 4*tc (covers 64)
    // ---- L2: At_b = silu(A1 @ R1 / 8)^T ----
    {
        float acc[4][4];
#pragma unroll
        for (int i = 0; i < 4; i++)
#pragma unroll
            for (int q = 0; q < 4; q++) acc[q][i] = 0.f;
#pragma unroll 8
        for (int k = 0; k < 64; k++) {
            float4 a = *(float4*)(At_a + k * 132 + te * 4);
            float4 b = *(float4*)(s_B + k * 64 + tc * 4);
            float av[4] = {a.x, a.y, a.z, a.w};
            float bv[4] = {b.x, b.y, b.z, b.w};
#pragma unroll
            for (int q = 0; q < 4; q++)
#pragma unroll
                for (int i = 0; i < 4; i++) acc[q][i] += av[i] * bv[q];
        }
#pragma unroll
        for (int q = 0; q < 4; q++) {
            float4 o;
            float s0 = acc[q][0] * 0.125f, s1 = acc[q][1] * 0.125f;
            float s2 = acc[q][2] * 0.125f, s3 = acc[q][3] * 0.125f;
            o.x = s0 / (1.f + __expf(-s0)); o.y = s1 / (1.f + __expf(-s1));
            o.z = s2 / (1.f + __expf(-s2)); o.w = s3 / (1.f + __expf(-s3));
            *(float4*)(At_b + (tc * 4 + q) * 132 + te * 4) = o;
        }
    }
    __syncthreads();
    for (int p = tid; p < 4096; p += 512) s_B[p] = R2[p];
    __syncthreads();
    // ---- L3: At_a = silu(A2 @ R2 / 8)^T ----
    {
        float acc[4][4];
#pragma unroll
        for (int i = 0; i < 4; i++)
#pragma unroll
            for (int q = 0; q < 4; q++) acc[q][i] = 0.f;
#pragma unroll 8
        for (int k = 0; k < 64; k++) {
            float4 a = *(float4*)(At_b + k * 132 + te * 4);
            float4 b = *(float4*)(s_B + k * 64 + tc * 4);
            float av[4] = {a.x, a.y, a.z, a.w};
            float bv[4] = {b.x, b.y, b.z, b.w};
#pragma unroll
            for (int q = 0; q < 4; q++)
#pragma unroll
                for (int i = 0; i < 4; i++) acc[q][i] += av[i] * bv[q];
        }
#pragma unroll
        for (int q = 0; q < 4; q++) {
            float4 o;
            float s0 = acc[q][0] * 0.125f, s1 = acc[q][1] * 0.125f;
            float s2 = acc[q][2] * 0.125f, s3 = acc[q][3] * 0.125f;
            o.x = s0 / (1.f + __expf(-s0)); o.y = s1 / (1.f + __expf(-s1));
            o.z = s2 / (1.f + __expf(-s2)); o.w = s3 / (1.f + __expf(-s3));
            *(float4*)(At_a + (tc * 4 + q) * 132 + te * 4) = o;
        }
    }
    __syncthreads();

    // ---- L4 chunks + scatter ----
    const int tu = tid >> 5;       // u-tile: u0 = 8*tu (covers 128)
    const int su = tid & 127;      // scatter channel
    const int sl = tid >> 7;       // scatter edge group
    for (int ch = 0; ch < 4; ch++) {
        // load R3 chunk [64][128]
        for (int p = tid; p < 2048; p += 512) {
            int k = p >> 5, c4 = (p & 31) << 2;
            *(float4*)(s_B + k * 128 + c4) =
                *(const float4*)(R3 + (size_t)k * 512 + ch * 128 + c4);
        }
        __syncthreads();
        // GEMM: s_w[u][e] = (A3 @ R3chunk / 8)
        {
            float acc[8][4];
#pragma unroll
            for (int q = 0; q < 8; q++)
#pragma unroll
                for (int i = 0; i < 4; i++) acc[q][i] = 0.f;
#pragma unroll 8
            for (int k = 0; k < 64; k++) {
                float4 a = *(float4*)(At_a + k * 132 + te * 4);
                float4 b0 = *(float4*)(s_B + k * 128 + tu * 8);
                float4 b1 = *(float4*)(s_B + k * 128 + tu * 8 + 4);
                float av[4] = {a.x, a.y, a.z, a.w};
                float bv[8] = {b0.x, b0.y, b0.z, b0.w, b1.x, b1.y, b1.z, b1.w};
#pragma unroll
                for (int q = 0; q < 8; q++)
#pragma unroll
                    for (int i = 0; i < 4; i++) acc[q][i] += av[i] * bv[q];
            }
#pragma unroll
            for (int q = 0; q < 8; q++) {
                float4 o = make_float4(acc[q][0] * 0.125f, acc[q][1] * 0.125f,
                                       acc[q][2] * 0.125f, acc[q][3] * 0.125f);
                *(float4*)(s_w + (tu * 8 + q) * 132 + te * 4) = o;
            }
        }
        __syncthreads();
        // scatter this chunk's contribution
        for (int e = sl; e < 128; e += 4) {
            int s = s_si[e];
            int r = s_ri[e];
            float w = s_w[su * 132 + e];
            float4 y = *(float4*)(s_y + e * 4);
            const float* hr = g_h + (size_t)s * 512;
            float* Mr = g_M + (size_t)r * 1024;
            if (ch == 0) {
                atomicAdd(Mr + su, w * hr[su] * y.x);
            } else if (ch == 1) {
                float t2 = w * hr[su];
                atomicAdd(Mr + 256 + su, t2 * y.y);
                atomicAdd(Mr + 512 + su, t2 * y.z);
                atomicAdd(Mr + 768 + su, t2 * y.w);
            } else if (ch == 2) {
                float wy = w * y.x;
                atomicAdd(Mr + 384 + su, wy * hr[128 + su]);
                atomicAdd(Mr + 640 + su, wy * hr[256 + su]);
                atomicAdd(Mr + 896 + su, wy * hr[384 + su]);
            } else {
                float d3 = hr[128 + su] * y.y + hr[256 + su] * y.z + hr[384 + su] * y.w;
                atomicAdd(Mr + 128 + su, w * d3 * 0.5773502691896258f);
            }
        }
        __syncthreads();
    }
}

// ---------------- final linear + density divide -> message output ----------
// grid (79, 4): j=0 -> out0 (W_lin0), j=1..3 -> out1[:,:,j-1] (W_lin1)
// 256 threads, K-chunked weights, 33KB static smem -> multi-block occupancy
__global__ __launch_bounds__(256) void lin_kernel(
        const float* __restrict__ Wl0, const float* __restrict__ Wl1,
        float* __restrict__ msg_out) {
    __shared__ float ych[32 * 132];  // 4224
    __shared__ float wb[32 * 128];   // 4096
    const int tid = threadIdx.x;
    const int j = blockIdx.y;
    const int nb = blockIdx.x * 128;
    const float* Wl = (j == 0) ? Wl0 : Wl1;

    const int tv = tid & 15, tn = tid >> 4;
    const int v0 = tv * 8, n0 = tn * 8;
    float acc[8][8];
#pragma unroll
    for (int i = 0; i < 8; i++)
#pragma unroll
        for (int q = 0; q < 8; q++) acc[i][q] = 0.f;

    for (int kc = 0; kc < 8; kc++) {
        for (int p = tid; p < 1024; p += 256)
            ((float4*)wb)[p] = ((const float4*)(Wl + kc * 4096))[p];
        for (int p = tid; p < 4096; p += 256) {
            int kk = p & 31, n = p >> 5;
            int gn = nb + n;
            ych[kk * 132 + n] =
                (gn < Nn) ? g_M[(size_t)gn * 1024 + j * 256 + kc * 32 + kk] : 0.f;
        }
        __syncthreads();
#pragma unroll 8
        for (int kk = 0; kk < 32; kk++) {
            float4 a0 = *(float4*)(ych + kk * 132 + n0);
            float4 a1 = *(float4*)(ych + kk * 132 + n0 + 4);
            float4 b0 = *(float4*)(wb + kk * 128 + v0);
            float4 b1 = *(float4*)(wb + kk * 128 + v0 + 4);
            float av[8] = {a0.x, a0.y, a0.z, a0.w, a1.x, a1.y, a1.z, a1.w};
            float bv[8] = {b0.x, b0.y, b0.z, b0.w, b1.x, b1.y, b1.z, b1.w};
#pragma unroll
            for (int i = 0; i < 8; i++)
#pragma unroll
                for (int q = 0; q < 8; q++) acc[i][q] += av[i] * bv[q];
        }
        __syncthreads();
    }
#pragma unroll
    for (int i = 0; i < 8; i++) {
        int gn = nb + n0 + i;
        if (gn < Nn) {
            float inv = 0.0625f / (g_dens[gn] + 1.f);  // 1/sqrt(256) / denom
#pragma unroll
            for (int q = 0; q < 8; q++)
                msg_out[(size_t)gn * 512 + (size_t)(v0 + q) * 4 + j] = acc[i][q] * inv;
        }
    }
}

extern "C" void kernel_launch(void* const* d_in, const int* in_sizes, int n_in,
                              void* d_out, int out_size) {
    const float* na   = (const float*)d_in[0];
    const float* nf   = (const float*)d_in[1];
    const float* ea   = (const float*)d_in[2];
    const float* ef   = (const float*)d_in[3];
    const int*   eidx = (const int*)d_in[4];
    const float* Wup0 = (const float*)d_in[5];
    const float* Wup1 = (const float*)d_in[6];
    const float* R0   = (const float*)d_in[7];
    const float* R1   = (const float*)d_in[8];
    const float* R2   = (const float*)d_in[9];
    const float* R3   = (const float*)d_in[10];
    const float* Wd   = (const float*)d_in[11];
    const float* Wl0  = (const float*)d_in[12];
    const float* Wl1  = (const float*)d_in[13];
    const float* Wsk0 = (const float*)d_in[14];
    const float* Wsk1 = (const float*)d_in[15];
    float* out = (float*)d_out;
    float* msg_out = out;                       // message: (N,128,4)
    float* sc_out  = out + (size_t)Nn * 512;    // sc: (N,512)

    cudaFuncSetAttribute(node_kernel, cudaFuncAttributeMaxDynamicSharedMemorySize, 104960);
    cudaFuncSetAttribute(edge_kernel, cudaFuncAttributeMaxDynamicSharedMemorySize, 178176);

    clear_kernel<<<2048, 256>>>();
    density_kernel<<<512, 256>>>(ef, Wd, eidx);
    node_kernel<<<dim3(79, 4), 256, 104960>>>(nf, na, Wup0, Wup1, Wsk0, Wsk1, sc_out);
    edge_kernel<<<1000, 512, 178176>>>(ef, ea, eidx, R0, R1, R2, R3);
    lin_kernel<<<dim3(79, 4), 256>>>(Wl0, Wl1, msg_out);
}

// round 3
// speedup vs baseline: 1.5719x; 1.2539x over previous
#include <cuda_runtime.h>
#include <math.h>

#define Nn 10000
#define Ee 128000

// ---------------- scratch (device globals: allocation-free) ----------------
__device__ float g_h[(size_t)Nn * 512];   // [n][0:128]=h0, [128+k*128+u]=h1[u,k]
__device__ float g_M[(size_t)Nn * 1024];  // [0:256]=M0, [256+k*256+c]=M1[c,k]
__device__ float g_dens[Nn];

// 16B vector reduction (sm_90+): 4 contiguous f32 adds in one LSU op
#define RED4(p, va, vb, vc, vd)                                         \
    asm volatile("red.global.add.v4.f32 [%0], {%1, %2, %3, %4};"        \
                 :: "l"(p), "f"(va), "f"(vb), "f"(vc), "f"(vd) : "memory")

// ---------------- clear accumulators ----------------
__global__ void clear_kernel() {
    int stride = gridDim.x * blockDim.x;
    int i = blockIdx.x * blockDim.x + threadIdx.x;
    float4 z = make_float4(0.f, 0.f, 0.f, 0.f);
    for (int p = i; p < Nn * 1024 / 4; p += stride) ((float4*)g_M)[p] = z;
    for (int p = i; p < Nn; p += stride) g_dens[p] = 0.f;
}

// ---------------- edge density + segment sum ----------------
__global__ void density_kernel(const float* __restrict__ ef,
                               const float* __restrict__ Wd,
                               const int* __restrict__ eidx) {
    float w[8];
#pragma unroll
    for (int k = 0; k < 8; k++) w[k] = __ldg(&Wd[k]);
    int stride = gridDim.x * blockDim.x;
    for (int e = blockIdx.x * blockDim.x + threadIdx.x; e < Ee; e += stride) {
        float t = 0.f;
#pragma unroll
        for (int k = 0; k < 8; k++) t += ef[(size_t)e * 8 + k] * w[k];
        t *= 0.35355339059327373f;  // 1/sqrt(8)
        atomicAdd(&g_dens[eidx[Ee + e]], tanhf(t * t));
    }
}

// ---------------- node kernel: up-projection (h) + skip (sc) ----------------
__global__ __launch_bounds__(256) void node_kernel(
        const float* __restrict__ nf, const float* __restrict__ na,
        const float* __restrict__ Wup0, const float* __restrict__ Wup1,
        const float* __restrict__ Wsk0, const float* __restrict__ Wsk1,
        float* __restrict__ sc_out) {
    extern __shared__ float sm[];
    float* xs  = sm;           // 128*128 = 16384
    float* ats = xs + 16384;   // 128*12  = 1536
    float* ych = ats + 1536;   // 32*132  = 4224
    float* wb  = ych + 4224;   // 32*128  = 4096

    const int tid = threadIdx.x;
    const int j = blockIdx.y;
    const int nb = blockIdx.x * 128;

    if (j == 0) {
        for (int p = tid; p < 4096; p += 256) {
            int n = p >> 5, u4 = (p & 31) << 2;
            int gn = nb + n;
            float4 v = make_float4(0.f, 0.f, 0.f, 0.f);
            if (gn < Nn) v = *(const float4*)(nf + (size_t)gn * 512 + u4);
            *(float4*)(xs + n * 128 + u4) = v;
        }
    } else {
        int kc2 = j - 1;
        for (int p = tid; p < 16384; p += 256) {
            int n = p >> 7, u = p & 127;
            int gn = nb + n;
            xs[p] = (gn < Nn) ? nf[(size_t)gn * 512 + 128 + u * 3 + kc2] : 0.f;
        }
    }
    for (int p = tid; p < 1280; p += 256) {
        int n = p / 10, a = p - n * 10;
        int gn = nb + n;
        ats[n * 12 + a] = (gn < Nn) ? na[(size_t)gn * 10 + a] : 0.f;
    }
    __syncthreads();

    const int tv = tid & 15, tn = tid >> 4;
    const int v0 = tv * 8, n0 = tn * 8;
    const float* Wup = (j == 0) ? Wup0 : Wup1;
    const float* Wsk = (j == 0) ? Wsk0 : Wsk1;

    float acc[8][8];
#pragma unroll
    for (int i = 0; i < 8; i++)
#pragma unroll
        for (int q = 0; q < 8; q++) acc[i][q] = 0.f;

    // ---- up projection: K = 128 ----
    for (int kc = 0; kc < 4; kc++) {
        for (int p = tid; p < 1024; p += 256)
            *(float4*)(wb + p * 4) = *(const float4*)(Wup + kc * 4096 + p * 4);
        for (int p = tid; p < 4096; p += 256) {
            int kk = p & 31, n = p >> 5;
            ych[kk * 132 + n] = xs[n * 128 + kc * 32 + kk];
        }
        __syncthreads();
#pragma unroll 8
        for (int kk = 0; kk < 32; kk++) {
            float4 a0 = *(float4*)(ych + kk * 132 + n0);
            float4 a1 = *(float4*)(ych + kk * 132 + n0 + 4);
            float4 b0 = *(float4*)(wb + kk * 128 + v0);
            float4 b1 = *(float4*)(wb + kk * 128 + v0 + 4);
            float av[8] = {a0.x, a0.y, a0.z, a0.w, a1.x, a1.y, a1.z, a1.w};
            float bv[8] = {b0.x, b0.y, b0.z, b0.w, b1.x, b1.y, b1.z, b1.w};
#pragma unroll
            for (int i = 0; i < 8; i++)
#pragma unroll
                for (int q = 0; q < 8; q++) acc[i][q] += av[i] * bv[q];
        }
        __syncthreads();
    }
    {
        const float s = 0.08838834764831845f;  // 1/sqrt(128)
#pragma unroll
        for (int i = 0; i < 8; i++) {
            int gn = nb + n0 + i;
            if (gn < Nn) {
                float* hp = g_h + (size_t)gn * 512 + j * 128 + v0;
#pragma unroll
                for (int q = 0; q < 8; q++) hp[q] = acc[i][q] * s;
            }
        }
    }

#pragma unroll
    for (int i = 0; i < 8; i++)
#pragma unroll
        for (int q = 0; q < 8; q++) acc[i][q] = 0.f;

    // ---- skip: K = 1280 over (u,a); A built on the fly = x[n,u]*attr[n,a] ----
    for (int kc = 0; kc < 40; kc++) {
        for (int p = tid; p < 1024; p += 256)
            *(float4*)(wb + p * 4) = *(const float4*)(Wsk + kc * 4096 + p * 4);
        for (int p = tid; p < 4096; p += 256) {
            int kk = p & 31, n = p >> 5;
            int ua = kc * 32 + kk;
            int u = ua / 10, a = ua - u * 10;
            ych[kk * 132 + n] = xs[n * 128 + u] * ats[n * 12 + a];
        }
        __syncthreads();
#pragma unroll 8
        for (int kk = 0; kk < 32; kk++) {
            float4 a0 = *(float4*)(ych + kk * 132 + n0);
            float4 a1 = *(float4*)(ych + kk * 132 + n0 + 4);
            float4 b0 = *(float4*)(wb + kk * 128 + v0);
            float4 b1 = *(float4*)(wb + kk * 128 + v0 + 4);
            float av[8] = {a0.x, a0.y, a0.z, a0.w, a1.x, a1.y, a1.z, a1.w};
            float bv[8] = {b0.x, b0.y, b0.z, b0.w, b1.x, b1.y, b1.z, b1.w};
#pragma unroll
            for (int i = 0; i < 8; i++)
#pragma unroll
                for (int q = 0; q < 8; q++) acc[i][q] += av[i] * bv[q];
        }
        __syncthreads();
    }
    {
        const float s = 0.027950849718747373f;  // 1/sqrt(1280)
#pragma unroll
        for (int i = 0; i < 8; i++) {
            int gn = nb + n0 + i;
            if (gn < Nn) {
                float* so = sc_out + (size_t)gn * 512;
                if (j == 0) {
#pragma unroll
                    for (int q = 0; q < 8; q++) so[v0 + q] = acc[i][q] * s;
                } else {
#pragma unroll
                    for (int q = 0; q < 8; q++) so[128 + (v0 + q) * 3 + (j - 1)] = acc[i][q] * s;
                }
            }
        }
    }
}

// ---------------- fused edge kernel: MLP (8->64->64->64->512) + scatter ----
// 512 threads, 128 edges per block, 110.6 KB smem -> 2 blocks/SM.
// L4 is computed per 128-col chunk (chunk ch == w_{ch+1}); each warp owns 8
// edges, each lane owns 4 contiguous channels, so w stays in registers and
// the scatter uses coalesced red.global.add.v4.f32 (4x fewer atomic ops).
__global__ __launch_bounds__(512, 2) void edge_kernel(
        const float* __restrict__ ef, const float* __restrict__ ea,
        const int* __restrict__ eidx,
        const float* __restrict__ R0, const float* __restrict__ R1,
        const float* __restrict__ R2, const float* __restrict__ R3) {
    extern __shared__ float sm[];
    float* s_ef = sm;                 // 1024
    float* s_r0 = sm + 1024;          // 512
    float* s_y  = sm + 1536;          // 512
    int*   s_si = (int*)(sm + 2048);  // 128
    int*   s_ri = (int*)(sm + 2176);  // 128
    float* At_a = sm + 2304;          // 64*132 = 8448  (A^T, [k][e])
    float* At_b = At_a + 8448;        // 8448
    float* s_B  = At_b + 8448;        // 8448 (R1/R2 64x64; R3 chunk 64x128)
    // total 27648 floats = 110592 B

    const int tid = threadIdx.x;
    const int eb = blockIdx.x * 128;

    // ---- stage inputs ----
    for (int p = tid; p < 256; p += 512)
        ((float4*)s_ef)[p] = ((const float4*)(ef + (size_t)eb * 8))[p];
    for (int p = tid; p < 128; p += 512)
        ((float4*)s_y)[p] = ((const float4*)(ea + (size_t)eb * 4))[p];
    if (tid < 128) {
        s_si[tid] = eidx[eb + tid];
        s_ri[tid] = eidx[Ee + eb + tid];
    }
    s_r0[tid] = R0[tid];
    for (int p = tid; p < 4096; p += 512) s_B[p] = R1[p];
    __syncthreads();

    // ---- L1: At_a[c][e] = silu(ef[e] . R0[:,c] / sqrt(8)) ----
    for (int p = tid; p < 8192; p += 512) {
        int c = p >> 7, e = p & 127;
        float s = 0.f;
#pragma unroll
        for (int k = 0; k < 8; k++) s += s_ef[e * 8 + k] * s_r0[k * 64 + c];
        s *= 0.35355339059327373f;
        At_a[c * 132 + e] = s / (1.f + __expf(-s));
    }
    __syncthreads();

    const int te = tid & 31;   // e-tile (L2/L3): e0 = 4*te
    const int tc = tid >> 5;   // c-tile (L2/L3): c0 = 4*tc
    // ---- L2: At_b = silu(A1 @ R1 / 8)^T ----
    {
        float acc2[4][4];
#pragma unroll
        for (int i = 0; i < 4; i++)
#pragma unroll
            for (int q = 0; q < 4; q++) acc2[q][i] = 0.f;
#pragma unroll 8
        for (int k = 0; k < 64; k++) {
            float4 a = *(float4*)(At_a + k * 132 + te * 4);
            float4 b = *(float4*)(s_B + k * 64 + tc * 4);
            float av[4] = {a.x, a.y, a.z, a.w};
            float bv[4] = {b.x, b.y, b.z, b.w};
#pragma unroll
            for (int q = 0; q < 4; q++)
#pragma unroll
                for (int i = 0; i < 4; i++) acc2[q][i] += av[i] * bv[q];
        }
#pragma unroll
        for (int q = 0; q < 4; q++) {
            float4 o;
            float s0 = acc2[q][0] * 0.125f, s1 = acc2[q][1] * 0.125f;
            float s2 = acc2[q][2] * 0.125f, s3 = acc2[q][3] * 0.125f;
            o.x = s0 / (1.f + __expf(-s0)); o.y = s1 / (1.f + __expf(-s1));
            o.z = s2 / (1.f + __expf(-s2)); o.w = s3 / (1.f + __expf(-s3));
            *(float4*)(At_b + (tc * 4 + q) * 132 + te * 4) = o;
        }
    }
    __syncthreads();
    for (int p = tid; p < 4096; p += 512) s_B[p] = R2[p];
    __syncthreads();
    // ---- L3: At_a = silu(A2 @ R2 / 8)^T ----
    {
        float acc2[4][4];
#pragma unroll
        for (int i = 0; i < 4; i++)
#pragma unroll
            for (int q = 0; q < 4; q++) acc2[q][i] = 0.f;
#pragma unroll 8
        for (int k = 0; k < 64; k++) {
            float4 a = *(float4*)(At_b + k * 132 + te * 4);
            float4 b = *(float4*)(s_B + k * 64 + tc * 4);
            float av[4] = {a.x, a.y, a.z, a.w};
            float bv[4] = {b.x, b.y, b.z, b.w};
#pragma unroll
            for (int q = 0; q < 4; q++)
#pragma unroll
                for (int i = 0; i < 4; i++) acc2[q][i] += av[i] * bv[q];
        }
#pragma unroll
        for (int q = 0; q < 4; q++) {
            float4 o;
            float s0 = acc2[q][0] * 0.125f, s1 = acc2[q][1] * 0.125f;
            float s2 = acc2[q][2] * 0.125f, s3 = acc2[q][3] * 0.125f;
            o.x = s0 / (1.f + __expf(-s0)); o.y = s1 / (1.f + __expf(-s1));
            o.z = s2 / (1.f + __expf(-s2)); o.w = s3 / (1.f + __expf(-s3));
            *(float4*)(At_a + (tc * 4 + q) * 132 + te * 4) = o;
        }
    }
    __syncthreads();

    // ---- L4 chunks + register scatter ----
    const int wrp = tid >> 5;        // warp: owns edges e0..e0+7
    const int lane = tid & 31;       // lane: owns channels 4*lane..4*lane+3
    const int e0 = wrp * 8;
    const int u4 = lane * 4;

#pragma unroll
    for (int ch = 0; ch < 4; ch++) {
        // load R3 chunk [64][128]
        for (int p = tid; p < 2048; p += 512) {
            int k = p >> 5, c4 = (p & 31) << 2;
            *(float4*)(s_B + k * 128 + c4) =
                *(const float4*)(R3 + (size_t)k * 512 + ch * 128 + c4);
        }
        __syncthreads();

        // GEMM: acc[i][j] = w[e0+i][u4+j] * 8  (scale applied at use)
        float acc[8][4];
#pragma unroll
        for (int i = 0; i < 8; i++)
#pragma unroll
            for (int q = 0; q < 4; q++) acc[i][q] = 0.f;
#pragma unroll 8
        for (int k = 0; k < 64; k++) {
            float4 a0 = *(float4*)(At_a + k * 132 + e0);
            float4 a1 = *(float4*)(At_a + k * 132 + e0 + 4);
            float4 b  = *(float4*)(s_B + k * 128 + u4);
            float av[8] = {a0.x, a0.y, a0.z, a0.w, a1.x, a1.y, a1.z, a1.w};
#pragma unroll
            for (int i = 0; i < 8; i++) {
                acc[i][0] += av[i] * b.x; acc[i][1] += av[i] * b.y;
                acc[i][2] += av[i] * b.z; acc[i][3] += av[i] * b.w;
            }
        }

        // scatter this chunk's contribution (coalesced v4 reductions)
#pragma unroll
        for (int i = 0; i < 8; i++) {
            int e = e0 + i;
            int s = s_si[e];
            int r = s_ri[e];
            float4 y = *(float4*)(s_y + e * 4);
            const float* hr = g_h + (size_t)s * 512;
            float* Mr = g_M + (size_t)r * 1024;
            float w0 = acc[i][0] * 0.125f, w1 = acc[i][1] * 0.125f;
            float w2 = acc[i][2] * 0.125f, w3 = acc[i][3] * 0.125f;
            if (ch == 0) {
                float4 h = *(const float4*)(hr + u4);
                RED4(Mr + u4, w0 * h.x * y.x, w1 * h.y * y.x,
                              w2 * h.z * y.x, w3 * h.w * y.x);
            } else if (ch == 1) {
                float4 h = *(const float4*)(hr + u4);
                float t0 = w0 * h.x, t1 = w1 * h.y, t2 = w2 * h.z, t3 = w3 * h.w;
                RED4(Mr + 256 + u4, t0 * y.y, t1 * y.y, t2 * y.y, t3 * y.y);
                RED4(Mr + 512 + u4, t0 * y.z, t1 * y.z, t2 * y.z, t3 * y.z);
                RED4(Mr + 768 + u4, t0 * y.w, t1 * y.w, t2 * y.w, t3 * y.w);
            } else if (ch == 2) {
                float4 ha = *(const float4*)(hr + 128 + u4);
                float4 hb = *(const float4*)(hr + 256 + u4);
                float4 hc = *(const float4*)(hr + 384 + u4);
                float wy0 = w0 * y.x, wy1 = w1 * y.x, wy2 = w2 * y.x, wy3 = w3 * y.x;
                RED4(Mr + 384 + u4, wy0 * ha.x, wy1 * ha.y, wy2 * ha.z, wy3 * ha.w);
                RED4(Mr + 640 + u4, wy0 * hb.x, wy1 * hb.y, wy2 * hb.z, wy3 * hb.w);
                RED4(Mr + 896 + u4, wy0 * hc.x, wy1 * hc.y, wy2 * hc.z, wy3 * hc.w);
            } else {
                float4 ha = *(const float4*)(hr + 128 + u4);
                float4 hb = *(const float4*)(hr + 256 + u4);
                float4 hc = *(const float4*)(hr + 384 + u4);
                const float c3 = 0.5773502691896258f;  // 1/sqrt(3)
                float d0 = ha.x * y.y + hb.x * y.z + hc.x * y.w;
                float d1 = ha.y * y.y + hb.y * y.z + hc.y * y.w;
                float d2 = ha.z * y.y + hb.z * y.z + hc.z * y.w;
                float d3 = ha.w * y.y + hb.w * y.z + hc.w * y.w;
                RED4(Mr + 128 + u4, w0 * d0 * c3, w1 * d1 * c3,
                                    w2 * d2 * c3, w3 * d3 * c3);
            }
        }
        __syncthreads();
    }
}

// ---------------- final linear + density divide -> message output ----------
__global__ __launch_bounds__(256) void lin_kernel(
        const float* __restrict__ Wl0, const float* __restrict__ Wl1,
        float* __restrict__ msg_out) {
    __shared__ float ych[32 * 132];  // 4224
    __shared__ float wb[32 * 128];   // 4096
    const int tid = threadIdx.x;
    const int j = blockIdx.y;
    const int nb = blockIdx.x * 128;
    const float* Wl = (j == 0) ? Wl0 : Wl1;

    const int tv = tid & 15, tn = tid >> 4;
    const int v0 = tv * 8, n0 = tn * 8;
    float acc[8][8];
#pragma unroll
    for (int i = 0; i < 8; i++)
#pragma unroll
        for (int q = 0; q < 8; q++) acc[i][q] = 0.f;

    for (int kc = 0; kc < 8; kc++) {
        for (int p = tid; p < 1024; p += 256)
            ((float4*)wb)[p] = ((const float4*)(Wl + kc * 4096))[p];
        for (int p = tid; p < 4096; p += 256) {
            int kk = p & 31, n = p >> 5;
            int gn = nb + n;
            ych[kk * 132 + n] =
                (gn < Nn) ? g_M[(size_t)gn * 1024 + j * 256 + kc * 32 + kk] : 0.f;
        }
        __syncthreads();
#pragma unroll 8
        for (int kk = 0; kk < 32; kk++) {
            float4 a0 = *(float4*)(ych + kk * 132 + n0);
            float4 a1 = *(float4*)(ych + kk * 132 + n0 + 4);
            float4 b0 = *(float4*)(wb + kk * 128 + v0);
            float4 b1 = *(float4*)(wb + kk * 128 + v0 + 4);
            float av[8] = {a0.x, a0.y, a0.z, a0.w, a1.x, a1.y, a1.z, a1.w};
            float bv[8] = {b0.x, b0.y, b0.z, b0.w, b1.x, b1.y, b1.z, b1.w};
#pragma unroll
            for (int i = 0; i < 8; i++)
#pragma unroll
                for (int q = 0; q < 8; q++) acc[i][q] += av[i] * bv[q];
        }
        __syncthreads();
    }
#pragma unroll
    for (int i = 0; i < 8; i++) {
        int gn = nb + n0 + i;
        if (gn < Nn) {
            float inv = 0.0625f / (g_dens[gn] + 1.f);  // 1/sqrt(256) / denom
#pragma unroll
            for (int q = 0; q < 8; q++)
                msg_out[(size_t)gn * 512 + (size_t)(v0 + q) * 4 + j] = acc[i][q] * inv;
        }
    }
}

extern "C" void kernel_launch(void* const* d_in, const int* in_sizes, int n_in,
                              void* d_out, int out_size) {
    const float* na   = (const float*)d_in[0];
    const float* nf   = (const float*)d_in[1];
    const float* ea   = (const float*)d_in[2];
    const float* ef   = (const float*)d_in[3];
    const int*   eidx = (const int*)d_in[4];
    const float* Wup0 = (const float*)d_in[5];
    const float* Wup1 = (const float*)d_in[6];
    const float* R0   = (const float*)d_in[7];
    const float* R1   = (const float*)d_in[8];
    const float* R2   = (const float*)d_in[9];
    const float* R3   = (const float*)d_in[10];
    const float* Wd   = (const float*)d_in[11];
    const float* Wl0  = (const float*)d_in[12];
    const float* Wl1  = (const float*)d_in[13];
    const float* Wsk0 = (const float*)d_in[14];
    const float* Wsk1 = (const float*)d_in[15];
    float* out = (float*)d_out;
    float* msg_out = out;                       // message: (N,128,4)
    float* sc_out  = out + (size_t)Nn * 512;    // sc: (N,512)

    cudaFuncSetAttribute(node_kernel, cudaFuncAttributeMaxDynamicSharedMemorySize, 104960);
    cudaFuncSetAttribute(edge_kernel, cudaFuncAttributeMaxDynamicSharedMemorySize, 110592);

    clear_kernel<<<2048, 256>>>();
    density_kernel<<<512, 256>>>(ef, Wd, eidx);
    node_kernel<<<dim3(79, 4), 256, 104960>>>(nf, na, Wup0, Wup1, Wsk0, Wsk1, sc_out);
    edge_kernel<<<1000, 512, 110592>>>(ef, ea, eidx, R0, R1, R2, R3);
    lin_kernel<<<dim3(79, 4), 256>>>(Wl0, Wl1, msg_out);
}

// round 5
// speedup vs baseline: 1.9950x; 1.2691x over previous
#include <cuda_runtime.h>
#include <cuda_bf16.h>
#include <mma.h>
#include <math.h>
#include <stdint.h>

using namespace nvcuda;

#define Nn 10000
#define Ee 128000

// ---------------- scratch (device globals: allocation-free) ----------------
__device__ float g_h[(size_t)Nn * 512];   // [n][0:128]=h0, [128+k*128+u]=h1[u,k]
__device__ float g_M[(size_t)Nn * 1024];  // [0:256]=M0, [256+k*256+c]=M1[c,k]
__device__ float g_dens[Nn];

// 16B vector reduction (sm_90+)
#define RED4(p, va, vb, vc, vd)                                         \
    asm volatile("red.global.add.v4.f32 [%0], {%1, %2, %3, %4};"        \
                 :: "l"(p), "f"(va), "f"(vb), "f"(vc), "f"(vd) : "memory")

// ---------------- clear accumulators ----------------
__global__ void clear_kernel() {
    int stride = gridDim.x * blockDim.x;
    int i = blockIdx.x * blockDim.x + threadIdx.x;
    float4 z = make_float4(0.f, 0.f, 0.f, 0.f);
    for (int p = i; p < Nn * 1024 / 4; p += stride) ((float4*)g_M)[p] = z;
    for (int p = i; p < Nn; p += stride) g_dens[p] = 0.f;
}

// ---------------- edge density + segment sum ----------------
__global__ void density_kernel(const float* __restrict__ ef,
                               const float* __restrict__ Wd,
                               const int* __restrict__ eidx) {
    float w[8];
#pragma unroll
    for (int k = 0; k < 8; k++) w[k] = __ldg(&Wd[k]);
    int stride = gridDim.x * blockDim.x;
    for (int e = blockIdx.x * blockDim.x + threadIdx.x; e < Ee; e += stride) {
        float t = 0.f;
#pragma unroll
        for (int k = 0; k < 8; k++) t += ef[(size_t)e * 8 + k] * w[k];
        t *= 0.35355339059327373f;
        atomicAdd(&g_dens[eidx[Ee + e]], tanhf(t * t));
    }
}

// ---------------- node kernel: wmma bf16-split GEMMs ----------------
// grid (79, 4), 256 threads (8 warps). Per block: M=128 nodes, N=128 outputs.
// up (K=128, 2 chunks of 64) then skip (K=1280, 20 chunks of 64).
// A/B tiles split to bf16 hi+lo on the fly; 3 wmma passes (hh, hl, lh) into
// fp32 accumulators => ~2^-16 effective input precision.
// SMEM layout (bytes):
//   0      xs   f32 [128][128]   65536
//   65536  ats  f32 [128][12]     6144
//   71680  tiles (73728): Ahi[128][72]bf16, Alo, Bhi[128][72]bf16, Blo
//          (each 18432 B) -- also overlaid as D f32 [128][128] after MMAs
#define NK_SM_TOTAL 145408
#define LDT 72
__global__ __launch_bounds__(256) void node_kernel(
        const float* __restrict__ nf, const float* __restrict__ na,
        const float* __restrict__ Wup0, const float* __restrict__ Wup1,
        const float* __restrict__ Wsk0, const float* __restrict__ Wsk1,
        float* __restrict__ sc_out) {
    extern __shared__ char smc[];
    float* xs  = (float*)smc;
    float* ats = (float*)(smc + 65536);
    __nv_bfloat16* Ahi = (__nv_bfloat16*)(smc + 71680);
    __nv_bfloat16* Alo = (__nv_bfloat16*)(smc + 71680 + 18432);
    __nv_bfloat16* Bhi = (__nv_bfloat16*)(smc + 71680 + 36864);
    __nv_bfloat16* Blo = (__nv_bfloat16*)(smc + 71680 + 55296);
    float* Dov = (float*)(smc + 71680);   // overlay, used after tiles are dead

    const int tid = threadIdx.x;
    const int wid = tid >> 5;
    const int j = blockIdx.y;
    const int nb = blockIdx.x * 128;
    const int m0 = wid * 16;

    // ---- stage x slab + attrs ----
    if (j == 0) {
        for (int p = tid; p < 4096; p += 256) {
            int n = p >> 5, u4 = (p & 31) << 2;
            int gn = nb + n;
            float4 v = make_float4(0.f, 0.f, 0.f, 0.f);
            if (gn < Nn) v = *(const float4*)(nf + (size_t)gn * 512 + u4);
            *(float4*)(xs + n * 128 + u4) = v;
        }
    } else {
        int kc2 = j - 1;
        for (int p = tid; p < 16384; p += 256) {
            int n = p >> 7, u = p & 127;
            int gn = nb + n;
            xs[p] = (gn < Nn) ? nf[(size_t)gn * 512 + 128 + u * 3 + kc2] : 0.f;
        }
    }
    for (int p = tid; p < 1280; p += 256) {
        int n = p / 10, a = p - n * 10;
        int gn = nb + n;
        ats[n * 12 + a] = (gn < Nn) ? na[(size_t)gn * 10 + a] : 0.f;
    }
    __syncthreads();

    const float* Wup = (j == 0) ? Wup0 : Wup1;
    const float* Wsk = (j == 0) ? Wsk0 : Wsk1;

    wmma::fragment<wmma::accumulator, 16, 16, 16, float> facc[8];
    wmma::fragment<wmma::matrix_a, 16, 16, 16, __nv_bfloat16, wmma::row_major> fah, fal;
    wmma::fragment<wmma::matrix_b, 16, 16, 16, __nv_bfloat16, wmma::col_major> fbh, fbl;

    // ================== PHASE LOOP: ph=0 up (2 chunks), ph=1 skip (20) =====
    for (int ph = 0; ph < 2; ph++) {
        const int nchunks = (ph == 0) ? 2 : 20;
        const float* W = (ph == 0) ? Wup : Wsk;
#pragma unroll
        for (int t = 0; t < 8; t++) wmma::fill_fragment(facc[t], 0.f);

        for (int c = 0; c < nchunks; c++) {
            const int k0 = c * 64;
            // ---- build A tile hi/lo: A[n][k] ----
            for (int p = tid; p < 2048; p += 256) {
                int n = p >> 4;
                int kk = (p & 15) << 2;
                float v0, v1, v2, v3;
                if (ph == 0) {
                    float4 v = *(float4*)(xs + n * 128 + k0 + kk);
                    v0 = v.x; v1 = v.y; v2 = v.z; v3 = v.w;
                } else {
                    int ua = k0 + kk;
                    int u0 = ua / 10, a0 = ua - u0 * 10;
                    int u1 = (ua + 1) / 10, a1 = (ua + 1) - u1 * 10;
                    int u2 = (ua + 2) / 10, a2 = (ua + 2) - u2 * 10;
                    int u3 = (ua + 3) / 10, a3 = (ua + 3) - u3 * 10;
                    const float* xr = xs + n * 128;
                    const float* ar = ats + n * 12;
                    v0 = xr[u0] * ar[a0]; v1 = xr[u1] * ar[a1];
                    v2 = xr[u2] * ar[a2]; v3 = xr[u3] * ar[a3];
                }
                __nv_bfloat16 h0 = __float2bfloat16(v0), h1 = __float2bfloat16(v1);
                __nv_bfloat16 h2 = __float2bfloat16(v2), h3 = __float2bfloat16(v3);
                __nv_bfloat16 l0 = __float2bfloat16(v0 - __bfloat162float(h0));
                __nv_bfloat16 l1 = __float2bfloat16(v1 - __bfloat162float(h1));
                __nv_bfloat16 l2 = __float2bfloat16(v2 - __bfloat162float(h2));
                __nv_bfloat16 l3 = __float2bfloat16(v3 - __bfloat162float(h3));
                int o = n * LDT + kk;
                Ahi[o] = h0; Ahi[o + 1] = h1; Ahi[o + 2] = h2; Ahi[o + 3] = h3;
                Alo[o] = l0; Alo[o + 1] = l1; Alo[o + 2] = l2; Alo[o + 3] = l3;
            }
            // ---- build B tile hi/lo: B[v][k] = W[k0+k][v] ----
            for (int p = tid; p < 2048; p += 256) {
                int v = p & 127;
                int kk = (p >> 7) << 2;
                const float* src = W + (size_t)(k0 + kk) * 128 + v;
                float v0 = src[0], v1 = src[128], v2 = src[256], v3 = src[384];
                __nv_bfloat16 h0 = __float2bfloat16(v0), h1 = __float2bfloat16(v1);
                __nv_bfloat16 h2 = __float2bfloat16(v2), h3 = __float2bfloat16(v3);
                __nv_bfloat16 l0 = __float2bfloat16(v0 - __bfloat162float(h0));
                __nv_bfloat16 l1 = __float2bfloat16(v1 - __bfloat162float(h1));
                __nv_bfloat16 l2 = __float2bfloat16(v2 - __bfloat162float(h2));
                __nv_bfloat16 l3 = __float2bfloat16(v3 - __bfloat162float(h3));
                int o = v * LDT + kk;
                Bhi[o] = h0; Bhi[o + 1] = h1; Bhi[o + 2] = h2; Bhi[o + 3] = h3;
                Blo[o] = l0; Blo[o + 1] = l1; Blo[o + 2] = l2; Blo[o + 3] = l3;
            }
            __syncthreads();
            // ---- MMA: 4 k16-steps x 8 n-tiles x 3 passes ----
#pragma unroll
            for (int kk = 0; kk < 4; kk++) {
                wmma::load_matrix_sync(fah, Ahi + m0 * LDT + kk * 16, LDT);
                wmma::load_matrix_sync(fal, Alo + m0 * LDT + kk * 16, LDT);
#pragma unroll
                for (int nt = 0; nt < 8; nt++) {
                    wmma::load_matrix_sync(fbh, Bhi + nt * 16 * LDT + kk * 16, LDT);
                    wmma::load_matrix_sync(fbl, Blo + nt * 16 * LDT + kk * 16, LDT);
                    wmma::mma_sync(facc[nt], fah, fbh, facc[nt]);
                    wmma::mma_sync(facc[nt], fah, fbl, facc[nt]);
                    wmma::mma_sync(facc[nt], fal, fbh, facc[nt]);
                }
            }
            __syncthreads();
        }

        // ---- store D to overlay (tiles now dead) ----
#pragma unroll
        for (int t = 0; t < 8; t++)
            wmma::store_matrix_sync(Dov + m0 * 128 + t * 16, facc[t], 128,
                                    wmma::mem_row_major);
        __syncthreads();

        // ---- write outputs ----
        if (ph == 0) {
            const float sh = 0.08838834764831845f;  // 1/sqrt(128)
            for (int p = tid; p < 4096; p += 256) {
                int n = p >> 5, v4 = (p & 31) << 2;
                int gn = nb + n;
                if (gn < Nn) {
                    float4 d = *(float4*)(Dov + n * 128 + v4);
                    float4 o = make_float4(d.x * sh, d.y * sh, d.z * sh, d.w * sh);
                    *(float4*)(g_h + (size_t)gn * 512 + j * 128 + v4) = o;
                }
            }
        } else {
            const float ss = 0.027950849718747373f;  // 1/sqrt(1280)
            if (j == 0) {
                for (int p = tid; p < 4096; p += 256) {
                    int n = p >> 5, v4 = (p & 31) << 2;
                    int gn = nb + n;
                    if (gn < Nn) {
                        float4 d = *(float4*)(Dov + n * 128 + v4);
                        float4 o = make_float4(d.x * ss, d.y * ss, d.z * ss, d.w * ss);
                        *(float4*)(sc_out + (size_t)gn * 512 + v4) = o;
                    }
                }
            } else {
                for (int p = tid; p < 16384; p += 256) {
                    int n = p >> 7, v = p & 127;
                    int gn = nb + n;
                    if (gn < Nn)
                        sc_out[(size_t)gn * 512 + 128 + v * 3 + (j - 1)] =
                            Dov[n * 128 + v] * ss;
                }
            }
        }
        __syncthreads();  // overlay dead before next phase rebuilds tiles
    }
}

// ---------------- fused edge kernel: MLP (8->64->64->64->512) + scatter ----
__global__ __launch_bounds__(512, 2) void edge_kernel(
        const float* __restrict__ ef, const float* __restrict__ ea,
        const int* __restrict__ eidx,
        const float* __restrict__ R0, const float* __restrict__ R1,
        const float* __restrict__ R2, const float* __restrict__ R3) {
    extern __shared__ float sm[];
    float* s_ef = sm;                 // 1024
    float* s_r0 = sm + 1024;          // 512
    float* s_y  = sm + 1536;          // 512
    int*   s_si = (int*)(sm + 2048);  // 128
    int*   s_ri = (int*)(sm + 2176);  // 128
    float* At_a = sm + 2304;          // 8448
    float* At_b = At_a + 8448;        // 8448
    float* s_B  = At_b + 8448;        // 8448

    const int tid = threadIdx.x;
    const int eb = blockIdx.x * 128;

    for (int p = tid; p < 256; p += 512)
        ((float4*)s_ef)[p] = ((const float4*)(ef + (size_t)eb * 8))[p];
    for (int p = tid; p < 128; p += 512)
        ((float4*)s_y)[p] = ((const float4*)(ea + (size_t)eb * 4))[p];
    if (tid < 128) {
        s_si[tid] = eidx[eb + tid];
        s_ri[tid] = eidx[Ee + eb + tid];
    }
    s_r0[tid] = R0[tid];
    for (int p = tid; p < 4096; p += 512) s_B[p] = R1[p];
    __syncthreads();

    for (int p = tid; p < 8192; p += 512) {
        int c = p >> 7, e = p & 127;
        float s = 0.f;
#pragma unroll
        for (int k = 0; k < 8; k++) s += s_ef[e * 8 + k] * s_r0[k * 64 + c];
        s *= 0.35355339059327373f;
        At_a[c * 132 + e] = s / (1.f + __expf(-s));
    }
    __syncthreads();

    const int te = tid & 31;
    const int tc = tid >> 5;
    {
        float acc2[4][4];
#pragma unroll
        for (int i = 0; i < 4; i++)
#pragma unroll
            for (int q = 0; q < 4; q++) acc2[q][i] = 0.f;
#pragma unroll 8
        for (int k = 0; k < 64; k++) {
            float4 a = *(float4*)(At_a + k * 132 + te * 4);
            float4 b = *(float4*)(s_B + k * 64 + tc * 4);
            float av[4] = {a.x, a.y, a.z, a.w};
            float bv[4] = {b.x, b.y, b.z, b.w};
#pragma unroll
            for (int q = 0; q < 4; q++)
#pragma unroll
                for (int i = 0; i < 4; i++) acc2[q][i] += av[i] * bv[q];
        }
#pragma unroll
        for (int q = 0; q < 4; q++) {
            float4 o;
            float s0 = acc2[q][0] * 0.125f, s1 = acc2[q][1] * 0.125f;
            float s2 = acc2[q][2] * 0.125f, s3 = acc2[q][3] * 0.125f;
            o.x = s0 / (1.f + __expf(-s0)); o.y = s1 / (1.f + __expf(-s1));
            o.z = s2 / (1.f + __expf(-s2)); o.w = s3 / (1.f + __expf(-s3));
            *(float4*)(At_b + (tc * 4 + q) * 132 + te * 4) = o;
        }
    }
    __syncthreads();
    for (int p = tid; p < 4096; p += 512) s_B[p] = R2[p];
    __syncthreads();
    {
        float acc2[4][4];
#pragma unroll
        for (int i = 0; i < 4; i++)
#pragma unroll
            for (int q = 0; q < 4; q++) acc2[q][i] = 0.f;
#pragma unroll 8
        for (int k = 0; k < 64; k++) {
            float4 a = *(float4*)(At_b + k * 132 + te * 4);
            float4 b = *(float4*)(s_B + k * 64 + tc * 4);
            float av[4] = {a.x, a.y, a.z, a.w};
            float bv[4] = {b.x, b.y, b.z, b.w};
#pragma unroll
            for (int q = 0; q < 4; q++)
#pragma unroll
                for (int i = 0; i < 4; i++) acc2[q][i] += av[i] * bv[q];
        }
#pragma unroll
        for (int q = 0; q < 4; q++) {
            float4 o;
            float s0 = acc2[q][0] * 0.125f, s1 = acc2[q][1] * 0.125f;
            float s2 = acc2[q][2] * 0.125f, s3 = acc2[q][3] * 0.125f;
            o.x = s0 / (1.f + __expf(-s0)); o.y = s1 / (1.f + __expf(-s1));
            o.z = s2 / (1.f + __expf(-s2)); o.w = s3 / (1.f + __expf(-s3));
            *(float4*)(At_a + (tc * 4 + q) * 132 + te * 4) = o;
        }
    }
    __syncthreads();

    const int wrp = tid >> 5;
    const int lane = tid & 31;
    const int e0 = wrp * 8;
    const int u4 = lane * 4;

#pragma unroll
    for (int ch = 0; ch < 4; ch++) {
        for (int p = tid; p < 2048; p += 512) {
            int k = p >> 5, c4 = (p & 31) << 2;
            *(float4*)(s_B + k * 128 + c4) =
                *(const float4*)(R3 + (size_t)k * 512 + ch * 128 + c4);
        }
        __syncthreads();

        float acc[8][4];
#pragma unroll
        for (int i = 0; i < 8; i++)
#pragma unroll
            for (int q = 0; q < 4; q++) acc[i][q] = 0.f;
#pragma unroll 8
        for (int k = 0; k < 64; k++) {
            float4 a0 = *(float4*)(At_a + k * 132 + e0);
            float4 a1 = *(float4*)(At_a + k * 132 + e0 + 4);
            float4 b  = *(float4*)(s_B + k * 128 + u4);
            float av[8] = {a0.x, a0.y, a0.z, a0.w, a1.x, a1.y, a1.z, a1.w};
#pragma unroll
            for (int i = 0; i < 8; i++) {
                acc[i][0] += av[i] * b.x; acc[i][1] += av[i] * b.y;
                acc[i][2] += av[i] * b.z; acc[i][3] += av[i] * b.w;
            }
        }

#pragma unroll
        for (int i = 0; i < 8; i++) {
            int e = e0 + i;
            int s = s_si[e];
            int r = s_ri[e];
            float4 y = *(float4*)(s_y + e * 4);
            const float* hr = g_h + (size_t)s * 512;
            float* Mr = g_M + (size_t)r * 1024;
            float w0 = acc[i][0] * 0.125f, w1 = acc[i][1] * 0.125f;
            float w2 = acc[i][2] * 0.125f, w3 = acc[i][3] * 0.125f;
            if (ch == 0) {
                float4 h = *(const float4*)(hr + u4);
                RED4(Mr + u4, w0 * h.x * y.x, w1 * h.y * y.x,
                              w2 * h.z * y.x, w3 * h.w * y.x);
            } else if (ch == 1) {
                float4 h = *(const float4*)(hr + u4);
                float t0 = w0 * h.x, t1 = w1 * h.y, t2 = w2 * h.z, t3 = w3 * h.w;
                RED4(Mr + 256 + u4, t0 * y.y, t1 * y.y, t2 * y.y, t3 * y.y);
                RED4(Mr + 512 + u4, t0 * y.z, t1 * y.z, t2 * y.z, t3 * y.z);
                RED4(Mr + 768 + u4, t0 * y.w, t1 * y.w, t2 * y.w, t3 * y.w);
            } else if (ch == 2) {
                float4 ha = *(const float4*)(hr + 128 + u4);
                float4 hb = *(const float4*)(hr + 256 + u4);
                float4 hc = *(const float4*)(hr + 384 + u4);
                float wy0 = w0 * y.x, wy1 = w1 * y.x, wy2 = w2 * y.x, wy3 = w3 * y.x;
                RED4(Mr + 384 + u4, wy0 * ha.x, wy1 * ha.y, wy2 * ha.z, wy3 * ha.w);
                RED4(Mr + 640 + u4, wy0 * hb.x, wy1 * hb.y, wy2 * hb.z, wy3 * hb.w);
                RED4(Mr + 896 + u4, wy0 * hc.x, wy1 * hc.y, wy2 * hc.z, wy3 * hc.w);
            } else {
                float4 ha = *(const float4*)(hr + 128 + u4);
                float4 hb = *(const float4*)(hr + 256 + u4);
                float4 hc = *(const float4*)(hr + 384 + u4);
                const float c3 = 0.5773502691896258f;
                float d0 = ha.x * y.y + hb.x * y.z + hc.x * y.w;
                float d1 = ha.y * y.y + hb.y * y.z + hc.y * y.w;
                float d2 = ha.z * y.y + hb.z * y.z + hc.z * y.w;
                float d3 = ha.w * y.y + hb.w * y.z + hc.w * y.w;
                RED4(Mr + 128 + u4, w0 * d0 * c3, w1 * d1 * c3,
                                    w2 * d2 * c3, w3 * d3 * c3);
            }
        }
        __syncthreads();
    }
}

// ---------------- final linear + density divide -> message output ----------
__global__ __launch_bounds__(256) void lin_kernel(
        const float* __restrict__ Wl0, const float* __restrict__ Wl1,
        float* __restrict__ msg_out) {
    __shared__ float ych[32 * 132];
    __shared__ float wb[32 * 128];
    const int tid = threadIdx.x;
    const int j = blockIdx.y;
    const int nb = blockIdx.x * 128;
    const float* Wl = (j == 0) ? Wl0 : Wl1;

    const int tv = tid & 15, tn = tid >> 4;
    const int v0 = tv * 8, n0 = tn * 8;
    float acc[8][8];
#pragma unroll
    for (int i = 0; i < 8; i++)
#pragma unroll
        for (int q = 0; q < 8; q++) acc[i][q] = 0.f;

    for (int kc = 0; kc < 8; kc++) {
        for (int p = tid; p < 1024; p += 256)
            ((float4*)wb)[p] = ((const float4*)(Wl + kc * 4096))[p];
        for (int p = tid; p < 4096; p += 256) {
            int kk = p & 31, n = p >> 5;
            int gn = nb + n;
            ych[kk * 132 + n] =
                (gn < Nn) ? g_M[(size_t)gn * 1024 + j * 256 + kc * 32 + kk] : 0.f;
        }
        __syncthreads();
#pragma unroll 8
        for (int kk = 0; kk < 32; kk++) {
            float4 a0 = *(float4*)(ych + kk * 132 + n0);
            float4 a1 = *(float4*)(ych + kk * 132 + n0 + 4);
            float4 b0 = *(float4*)(wb + kk * 128 + v0);
            float4 b1 = *(float4*)(wb + kk * 128 + v0 + 4);
            float av[8] = {a0.x, a0.y, a0.z, a0.w, a1.x, a1.y, a1.z, a1.w};
            float bv[8] = {b0.x, b0.y, b0.z, b0.w, b1.x, b1.y, b1.z, b1.w};
#pragma unroll
            for (int i = 0; i < 8; i++)
#pragma unroll
                for (int q = 0; q < 8; q++) acc[i][q] += av[i] * bv[q];
        }
        __syncthreads();
    }
#pragma unroll
    for (int i = 0; i < 8; i++) {
        int gn = nb + n0 + i;
        if (gn < Nn) {
            float inv = 0.0625f / (g_dens[gn] + 1.f);
#pragma unroll
            for (int q = 0; q < 8; q++)
                msg_out[(size_t)gn * 512 + (size_t)(v0 + q) * 4 + j] = acc[i][q] * inv;
        }
    }
}

extern "C" void kernel_launch(void* const* d_in, const int* in_sizes, int n_in,
                              void* d_out, int out_size) {
    const float* na   = (const float*)d_in[0];
    const float* nf   = (const float*)d_in[1];
    const float* ea   = (const float*)d_in[2];
    const float* ef   = (const float*)d_in[3];
    const int*   eidx = (const int*)d_in[4];
    const float* Wup0 = (const float*)d_in[5];
    const float* Wup1 = (const float*)d_in[6];
    const float* R0   = (const float*)d_in[7];
    const float* R1   = (const float*)d_in[8];
    const float* R2   = (const float*)d_in[9];
    const float* R3   = (const float*)d_in[10];
    const float* Wd   = (const float*)d_in[11];
    const float* Wl0  = (const float*)d_in[12];
    const float* Wl1  = (const float*)d_in[13];
    const float* Wsk0 = (const float*)d_in[14];
    const float* Wsk1 = (const float*)d_in[15];
    float* out = (float*)d_out;
    float* msg_out = out;                       // message: (N,128,4)
    float* sc_out  = out + (size_t)Nn * 512;    // sc: (N,512)

    cudaFuncSetAttribute(node_kernel, cudaFuncAttributeMaxDynamicSharedMemorySize, NK_SM_TOTAL);
    cudaFuncSetAttribute(edge_kernel, cudaFuncAttributeMaxDynamicSharedMemorySize, 110592);

    clear_kernel<<<2048, 256>>>();
    density_kernel<<<512, 256>>>(ef, Wd, eidx);
    node_kernel<<<dim3(79, 4), 256, NK_SM_TOTAL>>>(nf, na, Wup0, Wup1, Wsk0, Wsk1, sc_out);
    edge_kernel<<<1000, 512, 110592>>>(ef, ea, eidx, R0, R1, R2, R3);
    lin_kernel<<<dim3(79, 4), 256>>>(Wl0, Wl1, msg_out);
}